// round 1
// baseline (speedup 1.0000x reference)
#include <cuda_runtime.h>
#include <math.h>

// Problem shape (fixed by reference):
//   x  : (N, T, D) = (128, 512, 1024)
//   h0 : (N, H)    = (128, 1024)
//   Wx : (D, H)    = (1024, 1024)
//   Wh : (H, H)    = (1024, 1024)
//   b  : (H,)
//   out: (N, T, H) fp32
//
// Phase 1: out[n,t,:] = x[n,t,:] @ Wx + b      (one big GEMM, M = N*T = 65536)
// Phase 2: for t: out[:,t,:] = tanh(out[:,t,:] + h_{t-1} @ Wh), h_{t-1} = out[:,t-1,:] (or h0)

#define RNN_N 128
#define RNN_T 512
#define RNN_D 1024
#define RNN_H 1024

// ---------------------------------------------------------------------------
// Phase 1: C[M,H] = A[M,D] @ B[D,H] + bias   (M=65536, D=H=1024)
// Tile: BM=64, BN=64, BK=16, 256 threads, 4x4 microtile.
// ---------------------------------------------------------------------------
__global__ __launch_bounds__(256) void gemm_xw_kernel(
    const float* __restrict__ A,      // x as (M, D)
    const float* __restrict__ B,      // Wx (D, H)
    const float* __restrict__ bias,   // b (H)
    float* __restrict__ C)            // out (M, H)
{
    constexpr int BM = 64, BN = 64, BK = 16;
    __shared__ float As[BK][BM + 4];   // transposed A tile, padded (keeps 16B align)
    __shared__ float Bs[BK][BN];

    const int tid = threadIdx.x;
    const int block_row = blockIdx.y * BM;
    const int block_col = blockIdx.x * BN;

    const int tx = tid & 15;   // col group (0..15) -> cols tx*4 .. tx*4+3
    const int ty = tid >> 4;   // row group (0..15) -> rows ty*4 .. ty*4+3

    // A tile loads: 64 rows x 16 k, one float4 per thread
    const int a_r = tid >> 2;          // 0..63
    const int a_c = (tid & 3) * 4;     // 0,4,8,12
    // B tile loads: 16 k x 64 cols, one float4 per thread
    const int b_r = tid >> 4;          // 0..15
    const int b_c = (tid & 15) * 4;    // 0..60

    const float* Aptr = A + (size_t)block_row * RNN_D;
    const float* Bptr = B + block_col;

    float acc[4][4];
#pragma unroll
    for (int i = 0; i < 4; i++)
#pragma unroll
        for (int j = 0; j < 4; j++) acc[i][j] = 0.0f;

    for (int k0 = 0; k0 < RNN_D; k0 += BK) {
        float4 av = *(const float4*)(Aptr + (size_t)a_r * RNN_D + k0 + a_c);
        As[a_c + 0][a_r] = av.x;
        As[a_c + 1][a_r] = av.y;
        As[a_c + 2][a_r] = av.z;
        As[a_c + 3][a_r] = av.w;

        float4 bv = *(const float4*)(Bptr + (size_t)(k0 + b_r) * RNN_H + b_c);
        *(float4*)&Bs[b_r][b_c] = bv;

        __syncthreads();

#pragma unroll
        for (int k = 0; k < BK; ++k) {
            float4 a4 = *(const float4*)&As[k][ty * 4];
            float4 b4 = *(const float4*)&Bs[k][tx * 4];
            float ar[4] = {a4.x, a4.y, a4.z, a4.w};
            float br[4] = {b4.x, b4.y, b4.z, b4.w};
#pragma unroll
            for (int i = 0; i < 4; i++)
#pragma unroll
                for (int j = 0; j < 4; j++)
                    acc[i][j] = fmaf(ar[i], br[j], acc[i][j]);
        }
        __syncthreads();
    }

    float bb[4];
    *(float4*)bb = *(const float4*)(bias + block_col + tx * 4);

#pragma unroll
    for (int i = 0; i < 4; i++) {
        const int row = block_row + ty * 4 + i;
        float4 o;
        o.x = acc[i][0] + bb[0];
        o.y = acc[i][1] + bb[1];
        o.z = acc[i][2] + bb[2];
        o.w = acc[i][3] + bb[3];
        *(float4*)(C + (size_t)row * RNN_H + block_col + tx * 4) = o;
    }
}

// ---------------------------------------------------------------------------
// Phase 2 step: out_t[m, c] = tanh(out_t[m, c] + sum_k hprev[m, k] * Wh[k, c])
// M = 128 rows (batch), cols = H = 1024, K = H = 1024.
// Tile: BM=16, BN=64, BK=32, 256 threads, each thread 1 row x 4 cols.
// Grid: (H/BN = 16, M/BM = 8) = 128 CTAs (covers all SMs reasonably).
// hprev rows are strided by hprev_stride (H for h0, T*H for in-place out rows).
// ---------------------------------------------------------------------------
__global__ __launch_bounds__(256) void rnn_step_kernel(
    const float* __restrict__ hprev, size_t hprev_stride,
    const float* __restrict__ Wh,
    float* __restrict__ out_t, size_t out_stride)
{
    constexpr int BM = 16, BN = 64, BK = 32;
    __shared__ float As[BM][BK + 4];   // row-major A tile (scalar broadcast reads)
    __shared__ float Bs[BK][BN];

    const int tid = threadIdx.x;
    const int block_row = blockIdx.y * BM;
    const int block_col = blockIdx.x * BN;

    const int tx = tid & 15;   // col group -> cols tx*4..tx*4+3
    const int ty = tid >> 4;   // row 0..15

    // A loads: 16x32 = 512 floats = 128 float4 -> threads 0..127, one each
    const int a_r = tid >> 3;          // 0..15 (valid when tid < 128)
    const int a_c = (tid & 7) * 4;     // 0..28
    // B loads: 32x64 = 2048 floats = 512 float4 -> 2 per thread
    const int b_r = tid >> 4;          // 0..15 (second load at +16)
    const int b_c = (tid & 15) * 4;

    float acc[4] = {0.0f, 0.0f, 0.0f, 0.0f};

    const float* Bptr = Wh + block_col;

    for (int k0 = 0; k0 < RNN_H; k0 += BK) {
        if (tid < 128) {
            float4 av = *(const float4*)(hprev + (size_t)(block_row + a_r) * hprev_stride + k0 + a_c);
            *(float4*)&As[a_r][a_c] = av;
        }
        float4 bv0 = *(const float4*)(Bptr + (size_t)(k0 + b_r) * RNN_H + b_c);
        float4 bv1 = *(const float4*)(Bptr + (size_t)(k0 + b_r + 16) * RNN_H + b_c);
        *(float4*)&Bs[b_r][b_c] = bv0;
        *(float4*)&Bs[b_r + 16][b_c] = bv1;

        __syncthreads();

#pragma unroll
        for (int k = 0; k < BK; ++k) {
            const float a = As[ty][k];
            float4 b4 = *(const float4*)&Bs[k][tx * 4];
            acc[0] = fmaf(a, b4.x, acc[0]);
            acc[1] = fmaf(a, b4.y, acc[1]);
            acc[2] = fmaf(a, b4.z, acc[2]);
            acc[3] = fmaf(a, b4.w, acc[3]);
        }
        __syncthreads();
    }

    const int row = block_row + ty;
    float* optr = out_t + (size_t)row * out_stride + block_col + tx * 4;
    float4 xw = *(const float4*)optr;
    float4 o;
    o.x = tanhf(xw.x + acc[0]);
    o.y = tanhf(xw.y + acc[1]);
    o.z = tanhf(xw.z + acc[2]);
    o.w = tanhf(xw.w + acc[3]);
    *(float4*)optr = o;
}

// ---------------------------------------------------------------------------
// Launch
// ---------------------------------------------------------------------------
extern "C" void kernel_launch(void* const* d_in, const int* in_sizes, int n_in,
                              void* d_out, int out_size)
{
    const float* x  = (const float*)d_in[0];   // (N, T, D)
    const float* h0 = (const float*)d_in[1];   // (N, H)
    const float* Wx = (const float*)d_in[2];   // (D, H)
    const float* Wh = (const float*)d_in[3];   // (H, H)
    const float* b  = (const float*)d_in[4];   // (H)
    float* out = (float*)d_out;                // (N, T, H)

    // Phase 1: out = x @ Wx + b, M = N*T = 65536
    {
        dim3 grid(RNN_H / 64, (RNN_N * RNN_T) / 64);  // (16, 1024)
        gemm_xw_kernel<<<grid, 256>>>(x, Wx, b, out);
    }

    // Phase 2: sequential recurrence, in place on out
    {
        dim3 grid(RNN_H / 64, RNN_N / 16);            // (16, 8) = 128 CTAs
        for (int t = 0; t < RNN_T; ++t) {
            const float* hprev;
            size_t hstride;
            if (t == 0) {
                hprev = h0;
                hstride = RNN_H;
            } else {
                hprev = out + (size_t)(t - 1) * RNN_H;   // row n at + n*T*H
                hstride = (size_t)RNN_T * RNN_H;
            }
            rnn_step_kernel<<<grid, 256>>>(hprev, hstride, Wh,
                                           out + (size_t)t * RNN_H,
                                           (size_t)RNN_T * RNN_H);
        }
    }
}